// round 11
// baseline (speedup 1.0000x reference)
#include <cuda_runtime.h>

// SparseAbacusLayer: out[b,n] = prod_d (1 - interp1d(clip(act[b,:]), linspace(0,1,N_in), sp[n,d]))
// B=128, N_in=N_out=65536, degree=2.
//
// R11: main kernel is dynamic-instruction bound (occ/issue rose in lockstep
// R8->R10 with no dur change; mem pipes all <40%). Cut issues/output ~30%:
//  (a) 8 b per lane via LDG.128 on adjacent rows i0/i0+1 -> 4 loads/round
//      instead of 8.
//  (b) biased-domain lerp: keep 2^23+u after PRMT (no FADD); bias cancels in
//      the diff; epilogue fma(t,-S,C) with C = 1 + 2^23*S un-biases for free.

#define N_IN   65536
#define N_OUT  65536
#define NB     128

// clipped, transposed, u16-quantized activations: (N_in, B) -> 16 MB
__device__ __align__(16) unsigned short g_act16[N_IN * NB];

__device__ __forceinline__ float clip01(float v) {
    return fminf(fmaxf(v, 0.0f), 1.0f);
}

// u16 -> float 2^23 + u (exponent splice, no FADD; bias removed in epilogue)
__device__ __forceinline__ float prmtf(unsigned int w, unsigned int sel) {
    return __uint_as_float(__byte_perm(w, 0x4B000000u, sel));
}

// x[i] = fl(i * fl(1/65535)) matches jnp.linspace(0,1,65536,f32) exactly.
__device__ __forceinline__ void solve_point(float spv, int& idx, float& w) {
    const float DELTA = 1.0f / 65535.0f;
    spv = clip01(spv);
    int g = (int)(spv * 65535.0f);
    g = min(max(g, 0), 65535);
    while (g < 65535 && __fmul_rn((float)g, DELTA) < spv) ++g;
    while (g > 0 && __fmul_rn((float)(g - 1), DELTA) >= spv) --g;
    idx = max(g - 1, 0);                       // <= 65534
    float x0 = __fmul_rn((float)idx, DELTA);
    float x1 = __fmul_rn((float)(idx + 1), DELTA);
    float dx = __fadd_rn(__fsub_rn(x1, x0), 1e-8f);
    w = __fdiv_rn(__fsub_rn(spv, x0), dx);
}

// Clip+transpose+quantize: act (B,N_in) fp32 -> act16 (N_in,B) u16.
// Block (8,32) handles 32 n x ALL 128 b via four 32x33 tiles (MLP=4/thread).
__global__ void __launch_bounds__(256)
transpose_clip_kernel(const float* __restrict__ act) {
    __shared__ float tile[4][32][33];           // [b_tile][n_local][b_local]
    const int tx = threadIdx.x;                 // 0..7
    const int ty = threadIdx.y;                 // 0..31
    const int n0 = blockIdx.x * 32;

    float4 v[4];
    #pragma unroll
    for (int j = 0; j < 4; ++j)
        v[j] = __ldcs(reinterpret_cast<const float4*>(
            &act[(size_t)(32 * j + ty) * N_IN + n0 + 4 * tx]));

    #pragma unroll
    for (int j = 0; j < 4; ++j) {
        tile[j][4 * tx + 0][ty] = clip01(v[j].x);
        tile[j][4 * tx + 1][ty] = clip01(v[j].y);
        tile[j][4 * tx + 2][ty] = clip01(v[j].z);
        tile[j][4 * tx + 3][ty] = clip01(v[j].w);
    }
    __syncthreads();

    #pragma unroll
    for (int j = 0; j < 4; ++j) {
        unsigned int u0 = __float2uint_rn(tile[j][ty][4 * tx + 0] * 65535.0f);
        unsigned int u1 = __float2uint_rn(tile[j][ty][4 * tx + 1] * 65535.0f);
        unsigned int u2 = __float2uint_rn(tile[j][ty][4 * tx + 2] * 65535.0f);
        unsigned int u3 = __float2uint_rn(tile[j][ty][4 * tx + 3] * 65535.0f);
        uint2 p;
        p.x = u0 | (u1 << 16);
        p.y = u2 | (u3 << 16);
        *reinterpret_cast<uint2*>(
            &g_act16[(size_t)(n0 + ty) * NB + 32 * j + 4 * tx]) = p;
    }
}

// Main kernel: block = 32 consecutive n x all 128 b.
// Warp w owns n = 4w..4w+3. Two rounds; per round half-warp h handles
// n = 4w+2r+h, lane octet m (= lane&15) covers b = 8m..8m+7 via LDG.128
// on the adjacent row pair (i0, i0+1).
#define TSTR 132   // staging row stride in floats (128 + 4: bank-parity split)
__global__ void __launch_bounds__(256, 5)
interp_main_kernel(const float* __restrict__ sp, float* __restrict__ out) {
    __shared__ float tile[32 * TSTR];           // ~16.9 KB

    const int n0 = blockIdx.x * 32;
    const int tid = threadIdx.x;
    const int warp = tid >> 5;
    const int lane = tid & 31;
    const float S = 1.0f / 65535.0f;
    const float C = 1.0f + 8388608.0f * S;      // un-bias folded into epilogue

    // lanes 0..7: solve point p=lane: n = n0+4w+(p>>1), d = p&1
    int sidx = 0; float sw = 0.0f;
    if (lane < 8) {
        float spv = sp[(size_t)(n0 + 4 * warp + (lane >> 1)) * 2 + (lane & 1)];
        solve_point(spv, sidx, sw);
    }

    const int h = lane >> 4;                    // which n of the round's pair
    const int m = lane & 15;                    // b octet: b = 8m..8m+7
    const uint4* g = reinterpret_cast<const uint4*>(g_act16);  // row = 16 uint4

    #pragma unroll
    for (int r = 0; r < 2; ++r) {
        const int nl = 4 * warp + 2 * r + h;
        const int p  = (2 * r + h) * 2;
        int   ia = __shfl_sync(0xFFFFFFFFu, sidx, p);
        float wa = __shfl_sync(0xFFFFFFFFu, sw,   p);
        int   ib = __shfl_sync(0xFFFFFFFFu, sidx, p + 1);
        float wb = __shfl_sync(0xFFFFFFFFu, sw,   p + 1);

        uint4 A0 = __ldg(g + (size_t)ia * 16 + m);        // row ia,   8 b
        uint4 A1 = __ldg(g + (size_t)(ia + 1) * 16 + m);  // row ia+1
        uint4 B0 = __ldg(g + (size_t)ib * 16 + m);
        uint4 B1 = __ldg(g + (size_t)(ib + 1) * 16 + m);

        const unsigned int* pa0 = &A0.x;
        const unsigned int* pa1 = &A1.x;
        const unsigned int* pb0 = &B0.x;
        const unsigned int* pb1 = &B1.x;

        float res[8];
        #pragma unroll
        for (int j = 0; j < 4; ++j) {
            float a00l = prmtf(pa0[j], 0x7410), a00h = prmtf(pa0[j], 0x7432);
            float a01l = prmtf(pa1[j], 0x7410), a01h = prmtf(pa1[j], 0x7432);
            float b00l = prmtf(pb0[j], 0x7410), b00h = prmtf(pb0[j], 0x7432);
            float b01l = prmtf(pb1[j], 0x7410), b01h = prmtf(pb1[j], 0x7432);
            // biased lerp: bias cancels in the diff, stays in t
            float t0l = fmaf(a01l - a00l, wa, a00l);
            float t0h = fmaf(a01h - a00h, wa, a00h);
            float t1l = fmaf(b01l - b00l, wb, b00l);
            float t1h = fmaf(b01h - b00h, wb, b00h);
            res[2 * j]     = fmaf(t0l, -S, C) * fmaf(t1l, -S, C);
            res[2 * j + 1] = fmaf(t0h, -S, C) * fmaf(t1h, -S, C);
        }
        // STS.128 x2: quads = (nl + 2m + c) mod 32; halves differ in nl parity
        // -> disjoint parity sets, conflict-free.
        float4 lo = make_float4(res[0], res[1], res[2], res[3]);
        float4 hi = make_float4(res[4], res[5], res[6], res[7]);
        *reinterpret_cast<float4*>(&tile[nl * TSTR + 8 * m])     = lo;
        *reinterpret_cast<float4*>(&tile[nl * TSTR + 8 * m + 4]) = hi;
    }
    __syncthreads();

    // Output: thread (q = lane&7, bi = lane>>3) emits float4 along n for one b.
    const int q = lane & 7;
    const int bi = lane >> 3;
    #pragma unroll
    for (int it = 0; it < 4; ++it) {
        const int b = 4 * warp + bi + 32 * it;
        float vv[4];
        #pragma unroll
        for (int i = 0; i < 4; ++i) {
            // LDS.32: bank = (4q + i + b) mod 32 -> distinct over lanes
            vv[i] = tile[(4 * q + i) * TSTR + b];
        }
        float4 o = make_float4(vv[0], vv[1], vv[2], vv[3]);
        __stcs(reinterpret_cast<float4*>(&out[(size_t)b * N_OUT + n0 + 4 * q]), o);
    }
}

extern "C" void kernel_launch(void* const* d_in, const int* in_sizes, int n_in,
                              void* d_out, int out_size) {
    const float* act = (const float*)d_in[0];   // (128, 65536) fp32
    const float* sp  = (const float*)d_in[1];   // (65536, 2, 1) fp32
    float* out = (float*)d_out;                 // (128, 65536) fp32
    (void)in_sizes; (void)n_in; (void)out_size;

    transpose_clip_kernel<<<N_IN / 32, dim3(8, 32)>>>(act);
    interp_main_kernel<<<N_OUT / 32, 256>>>(sp, out);
}

// round 12
// speedup vs baseline: 1.0890x; 1.0890x over previous
#include <cuda_runtime.h>

// SparseAbacusLayer: out[b,n] = prod_d (1 - interp1d(clip(act[b,:]), linspace(0,1,N_in), sp[n,d]))
// B=128, N_in=N_out=65536, degree=2.
//
// R12 = R11's instruction cuts (LDG.128 gathers, biased-domain lerp) + FIXED
// conflict-free staging: stride 128, swizzle col = Q ^ (nl>>2) ^ (nl&1).
// The nl&1 term separates the two half-warp writers (R11's 4-way reader
// conflict came from dropping the swizzle).

#define N_IN   65536
#define N_OUT  65536
#define NB     128

// clipped, transposed, u16-quantized activations: (N_in, B) -> 16 MB
__device__ __align__(16) unsigned short g_act16[N_IN * NB];

__device__ __forceinline__ float clip01(float v) {
    return fminf(fmaxf(v, 0.0f), 1.0f);
}

// u16 -> float 2^23 + u (exponent splice, no FADD; bias removed in epilogue)
__device__ __forceinline__ float prmtf(unsigned int w, unsigned int sel) {
    return __uint_as_float(__byte_perm(w, 0x4B000000u, sel));
}

// x[i] = fl(i * fl(1/65535)) matches jnp.linspace(0,1,65536,f32) exactly.
__device__ __forceinline__ void solve_point(float spv, int& idx, float& w) {
    const float DELTA = 1.0f / 65535.0f;
    spv = clip01(spv);
    int g = (int)(spv * 65535.0f);
    g = min(max(g, 0), 65535);
    while (g < 65535 && __fmul_rn((float)g, DELTA) < spv) ++g;
    while (g > 0 && __fmul_rn((float)(g - 1), DELTA) >= spv) --g;
    idx = max(g - 1, 0);                       // <= 65534
    float x0 = __fmul_rn((float)idx, DELTA);
    float x1 = __fmul_rn((float)(idx + 1), DELTA);
    float dx = __fadd_rn(__fsub_rn(x1, x0), 1e-8f);
    w = __fdiv_rn(__fsub_rn(spv, x0), dx);
}

// Clip+transpose+quantize: act (B,N_in) fp32 -> act16 (N_in,B) u16.
__global__ void __launch_bounds__(256)
transpose_clip_kernel(const float* __restrict__ act) {
    __shared__ float tile[4][32][33];
    const int tx = threadIdx.x;                 // 0..7
    const int ty = threadIdx.y;                 // 0..31
    const int n0 = blockIdx.x * 32;

    float4 v[4];
    #pragma unroll
    for (int j = 0; j < 4; ++j)
        v[j] = __ldcs(reinterpret_cast<const float4*>(
            &act[(size_t)(32 * j + ty) * N_IN + n0 + 4 * tx]));

    #pragma unroll
    for (int j = 0; j < 4; ++j) {
        tile[j][4 * tx + 0][ty] = clip01(v[j].x);
        tile[j][4 * tx + 1][ty] = clip01(v[j].y);
        tile[j][4 * tx + 2][ty] = clip01(v[j].z);
        tile[j][4 * tx + 3][ty] = clip01(v[j].w);
    }
    __syncthreads();

    #pragma unroll
    for (int j = 0; j < 4; ++j) {
        unsigned int u0 = __float2uint_rn(tile[j][ty][4 * tx + 0] * 65535.0f);
        unsigned int u1 = __float2uint_rn(tile[j][ty][4 * tx + 1] * 65535.0f);
        unsigned int u2 = __float2uint_rn(tile[j][ty][4 * tx + 2] * 65535.0f);
        unsigned int u3 = __float2uint_rn(tile[j][ty][4 * tx + 3] * 65535.0f);
        uint2 p;
        p.x = u0 | (u1 << 16);
        p.y = u2 | (u3 << 16);
        *reinterpret_cast<uint2*>(
            &g_act16[(size_t)(n0 + ty) * NB + 32 * j + 4 * tx]) = p;
    }
}

// Main kernel: block = 32 consecutive n x all 128 b.
// Warp w owns n = 4w..4w+3, two rounds; half-warp h handles n = 4w+2r+h,
// lane octet m covers b = 8m..8m+7 via LDG.128 on adjacent rows (i, i+1).
// Staging: row nl stride 128, logical quad Q stored at col Q ^ (nl>>2) ^ (nl&1).
__global__ void __launch_bounds__(256, 5)
interp_main_kernel(const float* __restrict__ sp, float* __restrict__ out) {
    __shared__ float tile[32 * 128];            // 16 KB

    const int n0 = blockIdx.x * 32;
    const int tid = threadIdx.x;
    const int warp = tid >> 5;
    const int lane = tid & 31;
    const float S = 1.0f / 65535.0f;
    const float C = 1.0f + 8388608.0f * S;      // un-bias folded into epilogue

    // lanes 0..7: solve point p=lane: n = n0+4w+(p>>1), d = p&1
    int sidx = 0; float sw = 0.0f;
    if (lane < 8) {
        float spv = sp[(size_t)(n0 + 4 * warp + (lane >> 1)) * 2 + (lane & 1)];
        solve_point(spv, sidx, sw);
    }

    const int h = lane >> 4;                    // which n of the round's pair
    const int m = lane & 15;                    // b octet: b = 8m..8m+7
    const int sk = warp ^ h;                    // swizzle key = (nl>>2)^(nl&1)
    const uint4* g = reinterpret_cast<const uint4*>(g_act16);  // row = 16 uint4

    #pragma unroll
    for (int r = 0; r < 2; ++r) {
        const int nl = 4 * warp + 2 * r + h;
        const int p  = (2 * r + h) * 2;
        int   ia = __shfl_sync(0xFFFFFFFFu, sidx, p);
        float wa = __shfl_sync(0xFFFFFFFFu, sw,   p);
        int   ib = __shfl_sync(0xFFFFFFFFu, sidx, p + 1);
        float wb = __shfl_sync(0xFFFFFFFFu, sw,   p + 1);

        uint4 A0 = __ldg(g + (size_t)ia * 16 + m);        // row ia,   8 b
        uint4 A1 = __ldg(g + (size_t)(ia + 1) * 16 + m);  // row ia+1
        uint4 B0 = __ldg(g + (size_t)ib * 16 + m);
        uint4 B1 = __ldg(g + (size_t)(ib + 1) * 16 + m);

        const unsigned int* pa0 = &A0.x;
        const unsigned int* pa1 = &A1.x;
        const unsigned int* pb0 = &B0.x;
        const unsigned int* pb1 = &B1.x;

        float res[8];
        #pragma unroll
        for (int j = 0; j < 4; ++j) {
            float a00l = prmtf(pa0[j], 0x7410), a00h = prmtf(pa0[j], 0x7432);
            float a01l = prmtf(pa1[j], 0x7410), a01h = prmtf(pa1[j], 0x7432);
            float b00l = prmtf(pb0[j], 0x7410), b00h = prmtf(pb0[j], 0x7432);
            float b01l = prmtf(pb1[j], 0x7410), b01h = prmtf(pb1[j], 0x7432);
            // biased lerp: 2^23 bias cancels in the diff, stays in t
            float t0l = fmaf(a01l - a00l, wa, a00l);
            float t0h = fmaf(a01h - a00h, wa, a00h);
            float t1l = fmaf(b01l - b00l, wb, b00l);
            float t1h = fmaf(b01h - b00h, wb, b00h);
            res[2 * j]     = fmaf(t0l, -S, C) * fmaf(t1l, -S, C);
            res[2 * j + 1] = fmaf(t0h, -S, C) * fmaf(t1h, -S, C);
        }
        // STS.128 x2 at swizzled quad cols (2m)^sk, (2m+1)^sk.
        // h flips col parity -> half-warps disjoint -> conflict-free.
        float4 lo = make_float4(res[0], res[1], res[2], res[3]);
        float4 hi = make_float4(res[4], res[5], res[6], res[7]);
        *reinterpret_cast<float4*>(&tile[nl * 128 + 4 * ((2 * m) ^ sk)])       = lo;
        *reinterpret_cast<float4*>(&tile[nl * 128 + 4 * (((2 * m) | 1) ^ sk)]) = hi;
    }
    __syncthreads();

    // Output: thread (q = lane&7, bi = lane>>3) emits float4 along n for one b.
    const int q = lane & 7;
    const int bi = lane >> 3;
    #pragma unroll
    for (int it = 0; it < 4; ++it) {
        const int b = 4 * warp + bi + 32 * it;
        const int B = b >> 2;                   // = warp + 8*it (bi < 4)
        float vv[4];
        #pragma unroll
        for (int i = 0; i < 4; ++i) {
            // row = 4q+i, col = B ^ q ^ (i&1): distinct banks over (q,bi)
            vv[i] = tile[(4 * q + i) * 128 + 4 * (B ^ q ^ (i & 1)) + bi];
        }
        float4 o = make_float4(vv[0], vv[1], vv[2], vv[3]);
        __stcs(reinterpret_cast<float4*>(&out[(size_t)b * N_OUT + n0 + 4 * q]), o);
    }
}

extern "C" void kernel_launch(void* const* d_in, const int* in_sizes, int n_in,
                              void* d_out, int out_size) {
    const float* act = (const float*)d_in[0];   // (128, 65536) fp32
    const float* sp  = (const float*)d_in[1];   // (65536, 2, 1) fp32
    float* out = (float*)d_out;                 // (128, 65536) fp32
    (void)in_sizes; (void)n_in; (void)out_size;

    transpose_clip_kernel<<<N_IN / 32, dim3(8, 32)>>>(act);
    interp_main_kernel<<<N_OUT / 32, 256>>>(sp, out);
}